// round 5
// baseline (speedup 1.0000x reference)
#include <cuda_runtime.h>

// ----------------------------------------------------------------------------
// Problem constants
// ----------------------------------------------------------------------------
#define BATCH 256
#define SEQ 64
#define NG (BATCH*SEQ)          // 16384 graphs
#define NNODES 17
#define NEDGES 81               // 64 edges + 17 self loops
#define CIN0 3
#define HDIM 128                // HEADS*HID = 2*64
#define GROW (NNODES*HDIM)      // 2176 floats per graph
#define MROWS (NG*NNODES)       // 278528 node rows
#define LSTM_IN 2176
#define GATES 512               // 4*128

// ----------------------------------------------------------------------------
// Scratch (device globals). 16B-aligned for float4 access.
// ----------------------------------------------------------------------------
__device__ __align__(16) float g_bufA[NG * GROW];    // 142.6 MB
__device__ __align__(16) float g_bufB[NG * GROW];    // 142.6 MB
__device__ __align__(16) float g_tmpH[NG * GROW];    // 142.6 MB (pre-attention H)
__device__ __align__(16) float g_pre [NG * GATES];   // 33.5 MB
__device__ __align__(16) float g_h1  [NG * HDIM];    // 8.4 MB
__device__ __align__(16) float g_h2  [NG * HDIM];    // 8.4 MB
__device__ __align__(16) float g_hstate[BATCH * HDIM];
__device__ volatile unsigned g_bar_gen;
__device__ unsigned g_bar_cnt;

__device__ __forceinline__ const float* bufsel_r(int s)
{
    switch (s) {
        case 0: return g_bufA;
        case 1: return g_bufB;
        case 2: return g_tmpH;
        case 3: return g_h1;
        default: return g_pre;
    }
}
__device__ __forceinline__ float* bufsel_w(int s)
{
    switch (s) {
        case 0: return g_bufA;
        case 1: return g_bufB;
        case 2: return g_tmpH;
        default: return g_pre;
    }
}

// ----------------------------------------------------------------------------
// Grid barrier for the persistent LSTM kernel (128 CTAs < 148 SMs)
// ----------------------------------------------------------------------------
__device__ __forceinline__ void grid_barrier(unsigned nblocks)
{
    __syncthreads();
    if (threadIdx.x == 0) {
        __threadfence();
        unsigned gen = g_bar_gen;
        if (atomicAdd(&g_bar_cnt, 1u) == nblocks - 1u) {
            g_bar_cnt = 0u;
            __threadfence();
            g_bar_gen = gen + 1u;
        } else {
            while (g_bar_gen == gen) { __nanosleep(64); }
        }
    }
    __syncthreads();
}

// ----------------------------------------------------------------------------
// Layer-0 projection: H0[row,128] = x[row,0:3] @ W0[3,128]
// ----------------------------------------------------------------------------
__global__ void gat_mm0(const float* __restrict__ x, const float* __restrict__ W)
{
    __shared__ float sW[3 * 128];
    const int tid = threadIdx.x;
    for (int i = tid; i < 3 * 128; i += 256) sW[i] = W[i];
    __syncthreads();

    const long i = (long)blockIdx.x * 256 + tid;
    const long row = i >> 5;
    const int q = ((int)(i & 31)) << 2;
    const float x0 = x[row * 3 + 0];
    const float x1 = x[row * 3 + 1];
    const float x2 = x[row * 3 + 2];
    const float4 w0 = *(const float4*)&sW[0 * 128 + q];
    const float4 w1 = *(const float4*)&sW[1 * 128 + q];
    const float4 w2 = *(const float4*)&sW[2 * 128 + q];
    float4 o;
    o.x = x0 * w0.x + x1 * w1.x + x2 * w2.x;
    o.y = x0 * w0.y + x1 * w1.y + x2 * w2.y;
    o.z = x0 * w0.z + x1 * w1.z + x2 * w2.z;
    o.w = x0 * w0.w + x1 * w1.w + x2 * w2.w;
    *(float4*)&g_tmpH[row * 128 + q] = o;
}

// ----------------------------------------------------------------------------
// 128x128 block SGEMM, 256 threads, 8x8 per thread, BK=16, double-buffered.
// TRANSB=false: C = A[M,K] @ B[K,Nn]          TRANSB=true: C = A @ B^T + biases
// ----------------------------------------------------------------------------
template<bool TRANSB>
__global__ void __launch_bounds__(256, 2)
sgemm128(int a_sel, const float* __restrict__ Bmat,
         const float* __restrict__ bias1, const float* __restrict__ bias2,
         int out_sel, int M, int Nn, int K)
{
    const float* A = bufsel_r(a_sel);
    float* C = bufsel_w(out_sel);

    __shared__ __align__(16) float As[2][16][132];
    __shared__ __align__(16) float Bs[2][16][132];

    const int tid = threadIdx.x;
    const int tx = tid & 15;
    const int ty = tid >> 4;
    const int bm = blockIdx.x * 128;
    const int bn = blockIdx.y * 128;

    const int lr = tid >> 1;
    const int lk = (tid & 1) << 3;
    const float* Aptr = A + (long)(bm + lr) * K + lk;
    const int wr = tid >> 4;
    const int wc = (tid & 15) << 3;
    const float* Bptr;
    if (TRANSB) Bptr = Bmat + (long)(bn + lr) * K + lk;
    else        Bptr = Bmat + (long)wr * Nn + bn + wc;

    float acc[8][8];
    #pragma unroll
    for (int i = 0; i < 8; i++)
        #pragma unroll
        for (int j = 0; j < 8; j++) acc[i][j] = 0.f;

    const int NT = K >> 4;
    float pa[8], pb[8];

    {
        const float4 a0 = *(const float4*)(Aptr);
        const float4 a1 = *(const float4*)(Aptr + 4);
        pa[0]=a0.x; pa[1]=a0.y; pa[2]=a0.z; pa[3]=a0.w;
        pa[4]=a1.x; pa[5]=a1.y; pa[6]=a1.z; pa[7]=a1.w;
        const float4 b0 = *(const float4*)(Bptr);
        const float4 b1 = *(const float4*)(Bptr + 4);
        pb[0]=b0.x; pb[1]=b0.y; pb[2]=b0.z; pb[3]=b0.w;
        pb[4]=b1.x; pb[5]=b1.y; pb[6]=b1.z; pb[7]=b1.w;
    }
    #pragma unroll
    for (int i = 0; i < 8; i++) As[0][lk + i][lr] = pa[i];
    if (TRANSB) {
        #pragma unroll
        for (int i = 0; i < 8; i++) Bs[0][lk + i][lr] = pb[i];
    } else {
        *(float4*)&Bs[0][wr][wc]     = make_float4(pb[0], pb[1], pb[2], pb[3]);
        *(float4*)&Bs[0][wr][wc + 4] = make_float4(pb[4], pb[5], pb[6], pb[7]);
    }
    __syncthreads();

    int cur = 0;
    for (int kt = 0; kt < NT; kt++) {
        if (kt + 1 < NT) {
            const long ko = (long)(kt + 1) * 16;
            const float4 a0 = *(const float4*)(Aptr + ko);
            const float4 a1 = *(const float4*)(Aptr + ko + 4);
            pa[0]=a0.x; pa[1]=a0.y; pa[2]=a0.z; pa[3]=a0.w;
            pa[4]=a1.x; pa[5]=a1.y; pa[6]=a1.z; pa[7]=a1.w;
            const float4 b0 = TRANSB ? *(const float4*)(Bptr + ko)
                                     : *(const float4*)(Bptr + ko * Nn);
            const float4 b1 = TRANSB ? *(const float4*)(Bptr + ko + 4)
                                     : *(const float4*)(Bptr + ko * Nn + 4);
            pb[0]=b0.x; pb[1]=b0.y; pb[2]=b0.z; pb[3]=b0.w;
            pb[4]=b1.x; pb[5]=b1.y; pb[6]=b1.z; pb[7]=b1.w;
        }

        #pragma unroll
        for (int kk = 0; kk < 16; kk++) {
            float a[8], b[8];
            const float4 av0 = *(const float4*)&As[cur][kk][ty << 3];
            const float4 av1 = *(const float4*)&As[cur][kk][(ty << 3) + 4];
            a[0]=av0.x; a[1]=av0.y; a[2]=av0.z; a[3]=av0.w;
            a[4]=av1.x; a[5]=av1.y; a[6]=av1.z; a[7]=av1.w;
            const float4 bv0 = *(const float4*)&Bs[cur][kk][tx << 3];
            const float4 bv1 = *(const float4*)&Bs[cur][kk][(tx << 3) + 4];
            b[0]=bv0.x; b[1]=bv0.y; b[2]=bv0.z; b[3]=bv0.w;
            b[4]=bv1.x; b[5]=bv1.y; b[6]=bv1.z; b[7]=bv1.w;
            #pragma unroll
            for (int i = 0; i < 8; i++)
                #pragma unroll
                for (int j = 0; j < 8; j++)
                    acc[i][j] += a[i] * b[j];
        }

        if (kt + 1 < NT) {
            const int nxt = cur ^ 1;
            #pragma unroll
            for (int i = 0; i < 8; i++) As[nxt][lk + i][lr] = pa[i];
            if (TRANSB) {
                #pragma unroll
                for (int i = 0; i < 8; i++) Bs[nxt][lk + i][lr] = pb[i];
            } else {
                *(float4*)&Bs[nxt][wr][wc]     = make_float4(pb[0], pb[1], pb[2], pb[3]);
                *(float4*)&Bs[nxt][wr][wc + 4] = make_float4(pb[4], pb[5], pb[6], pb[7]);
            }
            __syncthreads();
            cur = nxt;
        }
    }

    #pragma unroll
    for (int i = 0; i < 8; i++) {
        const long row = bm + (ty << 3) + i;
        #pragma unroll
        for (int j = 0; j < 8; j += 4) {
            const int col = bn + (tx << 3) + j;
            float4 v = make_float4(acc[i][j], acc[i][j+1], acc[i][j+2], acc[i][j+3]);
            if (TRANSB) {
                v.x += bias1[col]     + bias2[col];
                v.y += bias1[col + 1] + bias2[col + 1];
                v.z += bias1[col + 2] + bias2[col + 2];
                v.w += bias1[col + 3] + bias2[col + 3];
            }
            *(float4*)&C[row * Nn + col] = v;
        }
    }
}

// ----------------------------------------------------------------------------
// GAT attention + aggregation, ONE WARP PER GRAPH. H read straight from
// g_tmpH (L1/L2-hot, re-read in aggregation); only alpha/logits in smem.
// Lane l owns dims [4l, 4l+4); head = l>=16 (matches hh*64+d dim layout).
// ----------------------------------------------------------------------------
__global__ void __launch_bounds__(256)
gat_attn(const float* __restrict__ a_src, const float* __restrict__ a_dst,
         const float* __restrict__ bias, const int* __restrict__ edge_index,
         int out_sel, int relu_flag)
{
    __shared__ float sAs[128], sAd[128], sB[128];
    __shared__ int s_src[NEDGES], s_dst[NEDGES], s_cs[NNODES + 1], s_ce[NEDGES];
    __shared__ float s_as[8][36];
    __shared__ float s_ad[8][36];
    __shared__ float s_m [8][36];
    __shared__ float s_dn[8][36];
    __shared__ float s_ev[8][164];

    const int tid = threadIdx.x;
    const int wid = tid >> 5, lane = tid & 31;

    if (tid < 128) { sAs[tid] = a_src[tid]; sAd[tid] = a_dst[tid]; sB[tid] = bias[tid]; }
    if (tid == 0) {
        int cnt[NNODES];
        for (int n = 0; n < NNODES; n++) cnt[n] = 0;
        for (int e = 0; e < NEDGES; e++) {
            int s = (e < 64) ? edge_index[e]      : (e - 64);
            int d = (e < 64) ? edge_index[64 + e] : (e - 64);
            s_src[e] = s; s_dst[e] = d; cnt[d]++;
        }
        int off = 0;
        for (int n = 0; n < NNODES; n++) { s_cs[n] = off; off += cnt[n]; cnt[n] = s_cs[n]; }
        s_cs[NNODES] = off;
        for (int e = 0; e < NEDGES; e++) s_ce[cnt[s_dst[e]]++] = e;
    }
    __syncthreads();

    const long g = (long)blockIdx.x * 8 + wid;
    const float* Hg = g_tmpH + g * GROW;
    float* outg = bufsel_w(out_sel) + g * GROW;

    const int hh = lane >> 4;
    const int q  = lane << 2;

    // phase 1: per-node logits via half-warp reductions
    #pragma unroll
    for (int n = 0; n < NNODES; n++) {
        const float4 hv = *(const float4*)&Hg[n * 128 + q];
        float pas = hv.x * sAs[q] + hv.y * sAs[q + 1] + hv.z * sAs[q + 2] + hv.w * sAs[q + 3];
        float pad_ = hv.x * sAd[q] + hv.y * sAd[q + 1] + hv.z * sAd[q + 2] + hv.w * sAd[q + 3];
        #pragma unroll
        for (int off = 8; off > 0; off >>= 1) {
            pas  += __shfl_xor_sync(0xffffffffu, pas, off);
            pad_ += __shfl_xor_sync(0xffffffffu, pad_, off);
        }
        if ((lane & 15) == 0) {
            s_as[wid][n * 2 + hh] = pas;
            s_ad[wid][n * 2 + hh] = pad_;
        }
    }
    __syncwarp();

    // phase 2: edge logits (leaky relu)
    for (int t = lane; t < 2 * NEDGES; t += 32) {
        const int e = t >> 1, h2 = t & 1;
        const float raw = s_as[wid][s_src[e] * 2 + h2] + s_ad[wid][s_dst[e] * 2 + h2];
        s_ev[wid][t] = raw > 0.f ? raw : 0.2f * raw;
    }
    __syncwarp();

    // per-dst max + denominator: 34 tasks on 32 lanes -> strided loop (R4 bug fix)
    for (int t = lane; t < 2 * NNODES; t += 32) {
        const int n = t >> 1, h2 = t & 1;
        float m = -1e30f;
        for (int p = s_cs[n]; p < s_cs[n + 1]; p++)
            m = fmaxf(m, s_ev[wid][s_ce[p] * 2 + h2]);
        float den = 0.f;
        for (int p = s_cs[n]; p < s_cs[n + 1]; p++)
            den += __expf(s_ev[wid][s_ce[p] * 2 + h2] - m);
        s_m[wid][t] = m; s_dn[wid][t] = den;
    }
    __syncwarp();

    // alpha
    for (int t = lane; t < 2 * NEDGES; t += 32) {
        const int e = t >> 1, h2 = t & 1;
        const int d = s_dst[e];
        s_ev[wid][t] = __expf(s_ev[wid][t] - s_m[wid][d * 2 + h2])
                       / (s_dn[wid][d * 2 + h2] + 1e-16f);
    }
    __syncwarp();

    // phase 3: aggregation + bias (+relu)
    const float4 b4 = *(const float4*)&sB[q];
    #pragma unroll
    for (int n = 0; n < NNODES; n++) {
        float4 acc = b4;
        for (int p = s_cs[n]; p < s_cs[n + 1]; p++) {
            const int e = s_ce[p];
            const float al = s_ev[wid][e * 2 + hh];
            const float4 hv = *(const float4*)&Hg[s_src[e] * 128 + q];
            acc.x += al * hv.x; acc.y += al * hv.y;
            acc.z += al * hv.z; acc.w += al * hv.w;
        }
        if (relu_flag) {
            acc.x = fmaxf(acc.x, 0.f); acc.y = fmaxf(acc.y, 0.f);
            acc.z = fmaxf(acc.z, 0.f); acc.w = fmaxf(acc.w, 0.f);
        }
        *(float4*)&outg[n * 128 + q] = acc;
    }
}

// ----------------------------------------------------------------------------
// LSTM recurrence (persistent, 128 CTAs). Thread map: l = tid>>3 (dim),
// row = tid&7 (batch row) => 8 lanes sharing each w row sit in one warp
// (LDS broadcast). sW stride 132 (16B-aligned rows) + float4 inner loop.
// ----------------------------------------------------------------------------
__global__ void lstm_recur(const float* __restrict__ whh, int out_sel)
{
    extern __shared__ __align__(16) float smem[];
    float* sW = smem;              // 128*132
    float* sH = sW + 128 * 132;    // 8*128
    float* sC = sH + 8 * 128;      // 8*32

    float* hseq = (out_sel == 0) ? g_h1 : g_h2;
    const float* pre = g_pre;

    const int tid = threadIdx.x;
    const int b0 = blockIdx.x * 8;
    const int d0 = blockIdx.y * 32;
    const unsigned nblocks = gridDim.x * gridDim.y;

    const int l   = tid >> 3;      // 0..31 hidden dim within slice
    const int row = tid & 7;       // 0..7 batch row

    // load whh slice: smem row r -> gate j = (r/32)*128 + d0 + (r%32)
    for (int i = tid; i < 128 * 128; i += blockDim.x) {
        const int r = i >> 7, k = i & 127;
        const int j = ((r >> 5) << 7) + d0 + (r & 31);
        sW[r * 132 + k] = whh[j * 128 + k];
    }
    sC[row * 32 + l] = 0.f;
    g_hstate[(b0 + row) * 128 + d0 + l] = 0.f;
    grid_barrier(nblocks);

    for (int t = 0; t < SEQ; t++) {
        for (int i = tid; i < 8 * 128; i += blockDim.x) {
            const int rr = i >> 7, k = i & 127;
            sH[i] = __ldcg(&g_hstate[(b0 + rr) * 128 + k]);
        }
        __syncthreads();

        {
            const float* hp = &sH[row * 128];
            const float* w0 = &sW[(l)      * 132];
            const float* w1 = &sW[(32 + l) * 132];
            const float* w2 = &sW[(64 + l) * 132];
            const float* w3 = &sW[(96 + l) * 132];
            const long pbase = ((long)(b0 + row) * SEQ + t) * GATES;
            float a0 = pre[pbase +       d0 + l];
            float a1 = pre[pbase + 128 + d0 + l];
            float a2 = pre[pbase + 256 + d0 + l];
            float a3 = pre[pbase + 384 + d0 + l];
            #pragma unroll 8
            for (int k4 = 0; k4 < 32; k4++) {
                const float4 hv  = *(const float4*)&hp[k4 * 4];
                const float4 wv0 = *(const float4*)&w0[k4 * 4];
                const float4 wv1 = *(const float4*)&w1[k4 * 4];
                const float4 wv2 = *(const float4*)&w2[k4 * 4];
                const float4 wv3 = *(const float4*)&w3[k4 * 4];
                a0 += hv.x * wv0.x + hv.y * wv0.y + hv.z * wv0.z + hv.w * wv0.w;
                a1 += hv.x * wv1.x + hv.y * wv1.y + hv.z * wv1.z + hv.w * wv1.w;
                a2 += hv.x * wv2.x + hv.y * wv2.y + hv.z * wv2.z + hv.w * wv2.w;
                a3 += hv.x * wv3.x + hv.y * wv3.y + hv.z * wv3.z + hv.w * wv3.w;
            }
            const float ig = 1.f / (1.f + expf(-a0));
            const float fg = 1.f / (1.f + expf(-a1));
            const float gg = tanhf(a2);
            const float og = 1.f / (1.f + expf(-a3));
            const float c = fg * sC[row * 32 + l] + ig * gg;
            sC[row * 32 + l] = c;
            const float h = og * tanhf(c);
            g_hstate[(b0 + row) * 128 + d0 + l] = h;
            hseq[((long)(b0 + row) * SEQ + t) * 128 + d0 + l] = h;
        }
        grid_barrier(nblocks);
    }
}

// ----------------------------------------------------------------------------
// Temporal attention + FC head. One CTA (128 threads) per batch row.
// ----------------------------------------------------------------------------
__global__ void attn_fc(const float* __restrict__ attn_w, const float* __restrict__ attn_b,
                        const float* __restrict__ fc_w,   const float* __restrict__ fc_b,
                        float* __restrict__ out)
{
    __shared__ float sw[128];
    __shared__ float sc[SEQ];
    __shared__ float sctx[128];

    const int b = blockIdx.x, tid = threadIdx.x;
    const float* h2 = g_h2 + (long)b * SEQ * 128;

    sw[tid] = attn_w[tid];
    __syncthreads();

    if (tid < SEQ) {
        const float* hp = h2 + tid * 128;
        float acc = attn_b[0];
        #pragma unroll 8
        for (int k = 0; k < 128; k++) acc += hp[k] * sw[k];
        sc[tid] = tanhf(acc);
    }
    __syncthreads();

    if (tid == 0) {
        float m = -1e30f;
        for (int t = 0; t < SEQ; t++) m = fmaxf(m, sc[t]);
        float s = 0.f;
        for (int t = 0; t < SEQ; t++) { sc[t] = __expf(sc[t] - m); s += sc[t]; }
        const float inv = 1.f / s;
        for (int t = 0; t < SEQ; t++) sc[t] *= inv;
    }
    __syncthreads();

    {
        float acc = 0.f;
        for (int t = 0; t < SEQ; t++) acc += sc[t] * h2[t * 128 + tid];
        sctx[tid] = acc;
    }
    __syncthreads();

    if (tid < 10) {
        float acc = fc_b[tid];
        #pragma unroll 8
        for (int k = 0; k < 128; k++) acc += sctx[k] * fc_w[tid * 128 + k];
        out[b * 10 + tid] = acc;
    }
}

// ----------------------------------------------------------------------------
// Launcher
// ----------------------------------------------------------------------------
extern "C" void kernel_launch(void* const* d_in, const int* in_sizes, int n_in,
                              void* d_out, int out_size)
{
    const float* x    = (const float*)d_in[0];
    const int*   eidx = (const int*)  d_in[1];
    const float* gw[4]  = { (const float*)d_in[2],  (const float*)d_in[6],
                            (const float*)d_in[10], (const float*)d_in[14] };
    const float* gas[4] = { (const float*)d_in[3],  (const float*)d_in[7],
                            (const float*)d_in[11], (const float*)d_in[15] };
    const float* gad[4] = { (const float*)d_in[4],  (const float*)d_in[8],
                            (const float*)d_in[12], (const float*)d_in[16] };
    const float* gb[4]  = { (const float*)d_in[5],  (const float*)d_in[9],
                            (const float*)d_in[13], (const float*)d_in[17] };
    const float* wih0 = (const float*)d_in[18];
    const float* whh0 = (const float*)d_in[19];
    const float* bih0 = (const float*)d_in[20];
    const float* bhh0 = (const float*)d_in[21];
    const float* wih1 = (const float*)d_in[22];
    const float* whh1 = (const float*)d_in[23];
    const float* bih1 = (const float*)d_in[24];
    const float* bhh1 = (const float*)d_in[25];
    const float* attn_w = (const float*)d_in[26];
    const float* attn_b = (const float*)d_in[27];
    const float* fc_w   = (const float*)d_in[28];
    const float* fc_b   = (const float*)d_in[29];
    float* out = (float*)d_out;

    const int smem_rec = (128 * 132 + 8 * 128 + 8 * 32) * 4;
    cudaFuncSetAttribute((const void*)lstm_recur,
                         cudaFuncAttributeMaxDynamicSharedMemorySize, smem_rec);

    const int attn_grid = NG / 8;        // 2048
    const int mm_grid   = MROWS / 128;   // 2176

    // ---- GAT layer 0: x @ W0 -> tmpH -> attn -> bufA (relu)
    gat_mm0<<<(MROWS * 32) / 256, 256>>>(x, gw[0]);
    gat_attn<<<attn_grid, 256>>>(gas[0], gad[0], gb[0], eidx, 0, 1);

    // ---- GAT layer 1: bufA @ W1 -> tmpH -> attn -> bufB
    sgemm128<false><<<dim3(mm_grid, 1), 256>>>(0, gw[1], nullptr, nullptr, 2, MROWS, 128, 128);
    gat_attn<<<attn_grid, 256>>>(gas[1], gad[1], gb[1], eidx, 1, 0);

    // ---- GAT layer 2: bufB @ W2 -> tmpH -> attn -> bufA (relu)
    sgemm128<false><<<dim3(mm_grid, 1), 256>>>(1, gw[2], nullptr, nullptr, 2, MROWS, 128, 128);
    gat_attn<<<attn_grid, 256>>>(gas[2], gad[2], gb[2], eidx, 0, 1);

    // ---- GAT layer 3: bufA @ W3 -> tmpH -> attn -> bufB
    sgemm128<false><<<dim3(mm_grid, 1), 256>>>(0, gw[3], nullptr, nullptr, 2, MROWS, 128, 128);
    gat_attn<<<attn_grid, 256>>>(gas[3], gad[3], gb[3], eidx, 1, 0);

    // ---- LSTM layer 0: pre-gates GEMM (A = bufB viewed [16384, 2176]) + recurrence
    sgemm128<true><<<dim3(NG / 128, GATES / 128), 256>>>(1, wih0, bih0, bhh0, 4, NG, GATES, LSTM_IN);
    lstm_recur<<<dim3(32, 4), 256, smem_rec>>>(whh0, 0);

    // ---- LSTM layer 1: pre-gates GEMM (A = g_h1 [16384,128]) + recurrence
    sgemm128<true><<<dim3(NG / 128, GATES / 128), 256>>>(3, wih1, bih1, bhh1, 4, NG, GATES, HDIM);
    lstm_recur<<<dim3(32, 4), 256, smem_rec>>>(whh1, 1);

    // ---- head
    attn_fc<<<BATCH, 128>>>(attn_w, attn_b, fc_w, fc_b, out);
}